// round 7
// baseline (speedup 1.0000x reference)
#include <cuda_runtime.h>
#include <cuda_bf16.h>
#include <cstdint>

#define B_   32
#define N_   512
#define K1_  256
#define O_   256
#define EPSF 1e-8f

// ---- GEMM tiling: CTA 128m x 128n, KC=16, 256 threads (8 warps, 2x4) ------
#define KC      16
#define A_ROW   48                        // 16 bf16 + 12B pad
#define A_PLANE (128 * A_ROW)             // 6144
#define B_ROW   272                       // 128 bf16 + 16B pad
#define B_PLANE (KC * B_ROW)              // 4352
#define AUX_SZ  2048
#define STAGE   (2 * A_PLANE + 2 * B_PLANE)   // 20992
#define OFF_AH  0
#define OFF_AL  A_PLANE
#define OFF_BH  (2 * A_PLANE)
#define OFF_BL  (2 * A_PLANE + B_PLANE)
#define SMEM_TOTAL (AUX_SZ + 2 * STAGE)       // 44032 -> 2 CTAs/SM

// ---- scratch: pre-split bf16 hi/lo planes -----------------------------------
__device__ __align__(16) float    g_dis[B_ * N_];
__device__ __align__(16) uint32_t g_AH[B_ * N_ * N_ / 2];   // A hi plane (bf16 pairs)
__device__ __align__(16) uint32_t g_AL[B_ * N_ * N_ / 2];   // A lo plane
__device__ __align__(16) uint32_t g_HH[B_ * N_ * K1_ / 2];  // H hi plane
__device__ __align__(16) uint32_t g_HL[B_ * N_ * K1_ / 2];  // H lo plane
__device__ __align__(16) uint32_t g_WH[K1_ * O_ / 2];       // W^T hi plane [k][o]
__device__ __align__(16) uint32_t g_WL[K1_ * O_ / 2];       // W^T lo plane
__device__ __align__(16) uint32_t g_HsH[B_ * N_ * O_ / 2];  // Hs hi plane [b][j][o]
__device__ __align__(16) uint32_t g_HsL[B_ * N_ * O_ / 2];  // Hs lo plane

// ---- helpers ------------------------------------------------------------------
__device__ __forceinline__ void ldsm_x4(uint32_t& r0, uint32_t& r1, uint32_t& r2,
                                        uint32_t& r3, uint32_t addr) {
    asm volatile("ldmatrix.sync.aligned.m8n8.x4.shared.b16 {%0,%1,%2,%3}, [%4];"
                 : "=r"(r0), "=r"(r1), "=r"(r2), "=r"(r3) : "r"(addr));
}
__device__ __forceinline__ void ldsm_x2t(uint32_t& r0, uint32_t& r1, uint32_t addr) {
    asm volatile("ldmatrix.sync.aligned.m8n8.x2.trans.shared.b16 {%0,%1}, [%2];"
                 : "=r"(r0), "=r"(r1) : "r"(addr));
}
__device__ __forceinline__ void mma16816(float* c,
                                         uint32_t a0, uint32_t a1, uint32_t a2, uint32_t a3,
                                         uint32_t b0, uint32_t b1) {
    asm volatile("mma.sync.aligned.m16n8k16.row.col.f32.bf16.bf16.f32 "
                 "{%0,%1,%2,%3}, {%4,%5,%6,%7}, {%8,%9}, {%0,%1,%2,%3};"
                 : "+f"(c[0]), "+f"(c[1]), "+f"(c[2]), "+f"(c[3])
                 : "r"(a0), "r"(a1), "r"(a2), "r"(a3), "r"(b0), "r"(b1));
}
__device__ __forceinline__ void split4(float4 f, uint2& hi, uint2& lo) {
    __nv_bfloat162 h01 = __floats2bfloat162_rn(f.x, f.y);
    __nv_bfloat162 h23 = __floats2bfloat162_rn(f.z, f.w);
    uint32_t u01 = *reinterpret_cast<uint32_t*>(&h01);
    uint32_t u23 = *reinterpret_cast<uint32_t*>(&h23);
    float r0 = f.x - __uint_as_float(u01 << 16);
    float r1 = f.y - __uint_as_float(u01 & 0xFFFF0000u);
    float r2 = f.z - __uint_as_float(u23 << 16);
    float r3 = f.w - __uint_as_float(u23 & 0xFFFF0000u);
    __nv_bfloat162 l01 = __floats2bfloat162_rn(r0, r1);
    __nv_bfloat162 l23 = __floats2bfloat162_rn(r2, r3);
    hi = make_uint2(u01, u23);
    lo = make_uint2(*reinterpret_cast<uint32_t*>(&l01), *reinterpret_cast<uint32_t*>(&l23));
}
// split a pair (v0, v1) -> (hi u32 pair, lo u32 pair)
__device__ __forceinline__ void split2(float v0, float v1, uint32_t& hu, uint32_t& lu) {
    __nv_bfloat162 h = __floats2bfloat162_rn(v0, v1);
    hu = *reinterpret_cast<uint32_t*>(&h);
    float r0 = v0 - __uint_as_float(hu << 16);
    float r1 = v1 - __uint_as_float(hu & 0xFFFF0000u);
    __nv_bfloat162 l = __floats2bfloat162_rn(r0, r1);
    lu = *reinterpret_cast<uint32_t*>(&l);
}

__device__ __forceinline__ void cpa16(uint32_t dst, const void* src) {
    asm volatile("cp.async.cg.shared.global [%0], [%1], 16;" :: "r"(dst), "l"(src));
}
#define CP_COMMIT() asm volatile("cp.async.commit_group;" ::: "memory")
#define CP_WAIT(n)  asm volatile("cp.async.wait_group %0;" :: "n"(n) : "memory")

// per-chunk mma: 3 split terms, warp tile 64x32, wm in {0,1}, wn in {0..3}
__device__ __forceinline__ void chunk_mma(float acc[4][4][4], uint32_t bufb,
                                          int wm, int wn, int lane) {
    const uint32_t arow = (uint32_t)((lane & 7) + ((lane >> 3) & 1) * 8);
    const uint32_t a_base = bufb + OFF_AH + (wm * 64 + arow) * A_ROW + (lane >> 4) * 16;
    const uint32_t b_base = bufb + OFF_BH + (lane & 15) * B_ROW + (wn * 32) * 2;

    uint32_t a[4][4], bh[4][2], bl[4][2];
#pragma unroll
    for (int mi = 0; mi < 4; mi++)
        ldsm_x4(a[mi][0], a[mi][1], a[mi][2], a[mi][3], a_base + mi * 16 * A_ROW);
#pragma unroll
    for (int n = 0; n < 4; n++) {
        ldsm_x2t(bh[n][0], bh[n][1], b_base + n * 16);
        ldsm_x2t(bl[n][0], bl[n][1], b_base + (OFF_BL - OFF_BH) + n * 16);
    }
#pragma unroll
    for (int mi = 0; mi < 4; mi++)
#pragma unroll
        for (int n = 0; n < 4; n++) {
            mma16816(acc[mi][n], a[mi][0], a[mi][1], a[mi][2], a[mi][3], bh[n][0], bh[n][1]);
            mma16816(acc[mi][n], a[mi][0], a[mi][1], a[mi][2], a[mi][3], bl[n][0], bl[n][1]);
        }
#pragma unroll
    for (int mi = 0; mi < 4; mi++)
        ldsm_x4(a[mi][0], a[mi][1], a[mi][2], a[mi][3],
                a_base + (OFF_AL - OFF_AH) + mi * 16 * A_ROW);
#pragma unroll
    for (int mi = 0; mi < 4; mi++)
#pragma unroll
        for (int n = 0; n < 4; n++)
            mma16816(acc[mi][n], a[mi][0], a[mi][1], a[mi][2], a[mi][3], bh[n][0], bh[n][1]);
}

// ---------------------------------------------------------------------------
// prep:
//  blocks [0,512):     A -> deg/dis + split planes (32 rows/block)
//  blocks [512,1024):  H -> split planes (32 rows/block)
//  blocks [1024,1088): W -> transpose + split planes (32x32 tiles)
// ---------------------------------------------------------------------------
__global__ __launch_bounds__(256)
void prep_kernel(const float* __restrict__ A, const float* __restrict__ H,
                 const float* __restrict__ W) {
    __shared__ float tile[32][33];
    const int t = threadIdx.x;
    if (blockIdx.x < 512) {
        int wid = t >> 5, lane = t & 31;
        int row0 = (blockIdx.x * 8 + wid) * 4;
        const float4* a = reinterpret_cast<const float4*>(A + (size_t)row0 * N_);
        uint2* ah = reinterpret_cast<uint2*>(g_AH);
        uint2* al = reinterpret_cast<uint2*>(g_AL);
        float s[4] = {0.f, 0.f, 0.f, 0.f};
#pragma unroll
        for (int c = 0; c < 4; c++)
#pragma unroll
            for (int r = 0; r < 4; r++) {
                float4 v = a[(size_t)r * 128 + lane + c * 32];
                s[r] += (v.x + v.y) + (v.z + v.w);
                uint2 hi, lo; split4(v, hi, lo);
                size_t p = (size_t)(row0 + r) * 128 + lane + c * 32;
                ah[p] = hi; al[p] = lo;
            }
#pragma unroll
        for (int o = 16; o > 0; o >>= 1)
#pragma unroll
            for (int r = 0; r < 4; r++) s[r] += __shfl_xor_sync(0xffffffffu, s[r], o);
        if (lane == 0)
#pragma unroll
            for (int r = 0; r < 4; r++) g_dis[row0 + r] = rsqrtf(s[r] + 1.0f + EPSF);
    } else if (blockIdx.x < 1024) {
        int wid = t >> 5, lane = t & 31;
        int row0 = ((blockIdx.x - 512) * 8 + wid) * 4;
        const float4* h = reinterpret_cast<const float4*>(H + (size_t)row0 * K1_);
        uint2* hh = reinterpret_cast<uint2*>(g_HH);
        uint2* hl = reinterpret_cast<uint2*>(g_HL);
#pragma unroll
        for (int c = 0; c < 2; c++)
#pragma unroll
            for (int r = 0; r < 4; r++) {
                float4 v = h[(size_t)r * 64 + lane + c * 32];
                uint2 hi, lo; split4(v, hi, lo);
                size_t p = (size_t)(row0 + r) * 64 + lane + c * 32;
                hh[p] = hi; hl[p] = lo;
            }
    } else {
        int idx = blockIdx.x - 1024;           // 64 tiles: 8x8
        int k0 = (idx & 7) * 32, o0 = (idx >> 3) * 32;
        int tx = t & 31, ty = t >> 5;          // (32, 8)
#pragma unroll
        for (int i = 0; i < 32; i += 8)
            tile[ty + i][tx] = W[(size_t)(o0 + ty + i) * K1_ + k0 + tx];
        __syncthreads();
        // write pairs along o: thread handles o-pairs (2*tx16..) — regroup: 16 pairs/row
        int txp = t & 15, typ = t >> 4;        // (16, 16)
#pragma unroll
        for (int i = 0; i < 32; i += 16) {
            int k = typ + i;
            float v0 = tile[txp * 2][k], v1 = tile[txp * 2 + 1][k];
            uint32_t hu, lu; split2(v0, v1, hu, lu);
            size_t p = ((size_t)(k0 + k) * O_ + o0 + txp * 2) >> 1;
            g_WH[p] = hu; g_WL[p] = lu;
        }
    }
}

// ---------------------------------------------------------------------------
// GEMM1: Hs[m,o] = dis[m]*(sum_k H[m,k] W[o,k] + b[o]); write Hs hi/lo planes.
// CTA 128x128, grid (128, 2), cp.async mainloop.
// ---------------------------------------------------------------------------
__global__ __launch_bounds__(256, 2)
void gemm1_mma(const float* __restrict__ bias) {
    extern __shared__ char smem[];
    const uint32_t sb = (uint32_t)__cvta_generic_to_shared(smem);
    const int t = threadIdx.x, lane = t & 31, wid = t >> 5;
    const int wm = wid >> 2, wn = wid & 3;
    const int bm = blockIdx.x * 128;
    const int bn = blockIdx.y * 128;

    float* bias_s = reinterpret_cast<float*>(smem);
    float* dis_s  = reinterpret_cast<float*>(smem + 1024);
    if (t < 128) { bias_s[t] = bias[bn + t]; dis_s[t] = g_dis[bm + t]; }

    // cp.async source pointers (bytes)
    const char* aH = reinterpret_cast<const char*>(g_HH)
                   + (size_t)(bm + (t >> 1)) * 512 + (t & 1) * 16;   // H row = 512B
    const char* aL = reinterpret_cast<const char*>(g_HL)
                   + (size_t)(bm + (t >> 1)) * 512 + (t & 1) * 16;
    const char* bH = reinterpret_cast<const char*>(g_WH)
                   + (size_t)(t >> 4) * 512 + (bn + (t & 15) * 8) * 2; // W^T row = 512B
    const char* bL = reinterpret_cast<const char*>(g_WL)
                   + (size_t)(t >> 4) * 512 + (bn + (t & 15) * 8) * 2;
    const uint32_t a_d = sb + AUX_SZ + OFF_AH + (t >> 1) * A_ROW + (t & 1) * 16;
    const uint32_t b_d = sb + AUX_SZ + OFF_BH + (t >> 4) * B_ROW + (t & 15) * 16;

    float acc[4][4][4];
#pragma unroll
    for (int i = 0; i < 4; i++)
#pragma unroll
        for (int j = 0; j < 4; j++)
#pragma unroll
            for (int e = 0; e < 4; e++) acc[i][j][e] = 0.f;

    const int S = K1_ / KC;  // 16
    // prologue
    cpa16(a_d, aH); cpa16(a_d + (OFF_AL - OFF_AH), aL);
    cpa16(b_d, bH); cpa16(b_d + (OFF_BL - OFF_BH), bL);
    CP_COMMIT();

    for (int s = 0; s < S; s++) {
        if (s + 1 < S) {
            uint32_t st = (uint32_t)((s + 1) & 1) * STAGE;
            cpa16(a_d + st, aH + (s + 1) * 32);
            cpa16(a_d + st + (OFF_AL - OFF_AH), aL + (s + 1) * 32);
            cpa16(b_d + st, bH + (size_t)(s + 1) * 8192);
            cpa16(b_d + st + (OFF_BL - OFF_BH), bL + (size_t)(s + 1) * 8192);
            CP_COMMIT();
            CP_WAIT(1);
        } else {
            CP_WAIT(0);
        }
        __syncthreads();
        chunk_mma(acc, sb + AUX_SZ + (uint32_t)(s & 1) * STAGE, wm, wn, lane);
        __syncthreads();
    }

    // epilogue: +bias, *dis, split into Hs planes
    const int g = lane >> 2, i4 = lane & 3;
#pragma unroll
    for (int mi = 0; mi < 4; mi++) {
        int r0 = wm * 64 + mi * 16 + g;
        float d0 = dis_s[r0], d1 = dis_s[r0 + 8];
        size_t base0 = ((size_t)(bm + r0) * O_ + bn);
        size_t base1 = base0 + 8 * O_;
#pragma unroll
        for (int n = 0; n < 4; n++) {
            int o = wn * 32 + n * 8 + i4 * 2;
            float b0 = bias_s[o], b1 = bias_s[o + 1];
            uint32_t hu, lu;
            split2((acc[mi][n][0] + b0) * d0, (acc[mi][n][1] + b1) * d0, hu, lu);
            g_HsH[(base0 + o) >> 1] = hu; g_HsL[(base0 + o) >> 1] = lu;
            split2((acc[mi][n][2] + b0) * d1, (acc[mi][n][3] + b1) * d1, hu, lu);
            g_HsH[(base1 + o) >> 1] = hu; g_HsL[(base1 + o) >> 1] = lu;
        }
    }
}

// ---------------------------------------------------------------------------
// GEMM2: out[b,i,o] = relu(mask*dis_i*(sum_j A[i,j] Hs[j,o] + Hs[i,o])).
// CTA 128x128, grid (4, 2, 32), cp.async mainloop.
// ---------------------------------------------------------------------------
__global__ __launch_bounds__(256, 2)
void gemm2_mma(const float* __restrict__ mask, float* __restrict__ out) {
    extern __shared__ char smem[];
    const uint32_t sb = (uint32_t)__cvta_generic_to_shared(smem);
    const int t = threadIdx.x, lane = t & 31, wid = t >> 5;
    const int wm = wid >> 2, wn = wid & 3;
    const int i0 = blockIdx.x * 128;
    const int bn = blockIdx.y * 128;
    const int b  = blockIdx.z;

    float* mdis_s = reinterpret_cast<float*>(smem);
    if (t < 128) mdis_s[t] = mask[b * N_ + i0 + t] * g_dis[b * N_ + i0 + t];

    const size_t gi = (size_t)(b * N_ + i0 + (t >> 1));
    const char* aH = reinterpret_cast<const char*>(g_AH) + gi * 1024 + (t & 1) * 16;  // A row = 1024B
    const char* aL = reinterpret_cast<const char*>(g_AL) + gi * 1024 + (t & 1) * 16;
    const char* bH = reinterpret_cast<const char*>(g_HsH)
                   + ((size_t)b * N_ + (t >> 4)) * 512 + (bn + (t & 15) * 8) * 2;     // Hs row = 512B
    const char* bL = reinterpret_cast<const char*>(g_HsL)
                   + ((size_t)b * N_ + (t >> 4)) * 512 + (bn + (t & 15) * 8) * 2;
    const uint32_t a_d = sb + AUX_SZ + OFF_AH + (t >> 1) * A_ROW + (t & 1) * 16;
    const uint32_t b_d = sb + AUX_SZ + OFF_BH + (t >> 4) * B_ROW + (t & 15) * 16;

    float acc[4][4][4];
#pragma unroll
    for (int i = 0; i < 4; i++)
#pragma unroll
        for (int j = 0; j < 4; j++)
#pragma unroll
            for (int e = 0; e < 4; e++) acc[i][j][e] = 0.f;

    const int S = N_ / KC;  // 32
    cpa16(a_d, aH); cpa16(a_d + (OFF_AL - OFF_AH), aL);
    cpa16(b_d, bH); cpa16(b_d + (OFF_BL - OFF_BH), bL);
    CP_COMMIT();

    for (int s = 0; s < S; s++) {
        if (s + 1 < S) {
            uint32_t st = (uint32_t)((s + 1) & 1) * STAGE;
            cpa16(a_d + st, aH + (s + 1) * 32);
            cpa16(a_d + st + (OFF_AL - OFF_AH), aL + (s + 1) * 32);
            cpa16(b_d + st, bH + (size_t)(s + 1) * 8192);
            cpa16(b_d + st + (OFF_BL - OFF_BH), bL + (size_t)(s + 1) * 8192);
            CP_COMMIT();
            CP_WAIT(1);
        } else {
            CP_WAIT(0);
        }
        __syncthreads();
        chunk_mma(acc, sb + AUX_SZ + (uint32_t)(s & 1) * STAGE, wm, wn, lane);
        __syncthreads();
    }

    // epilogue: + self-loop Hs[i,o] (hi+lo planes), * mask*dis_i, relu
    const int g = lane >> 2, i4 = lane & 3;
#pragma unroll
    for (int mi = 0; mi < 4; mi++) {
        int r0 = wm * 64 + mi * 16 + g;
        float md0 = mdis_s[r0], md1 = mdis_s[r0 + 8];
        size_t row0 = ((size_t)b * N_ + i0 + r0) * O_ + bn;
        size_t row1 = row0 + 8 * O_;
#pragma unroll
        for (int n = 0; n < 4; n++) {
            int o = wn * 32 + n * 8 + i4 * 2;
            uint32_t qh0 = g_HsH[(row0 + o) >> 1], ql0 = g_HsL[(row0 + o) >> 1];
            uint32_t qh1 = g_HsH[(row1 + o) >> 1], ql1 = g_HsL[(row1 + o) >> 1];
            float s00 = __uint_as_float(qh0 << 16) + __uint_as_float(ql0 << 16);
            float s01 = __uint_as_float(qh0 & 0xFFFF0000u) + __uint_as_float(ql0 & 0xFFFF0000u);
            float s10 = __uint_as_float(qh1 << 16) + __uint_as_float(ql1 << 16);
            float s11 = __uint_as_float(qh1 & 0xFFFF0000u) + __uint_as_float(ql1 & 0xFFFF0000u);
            out[row0 + o]     = fmaxf(0.f, md0 * (acc[mi][n][0] + s00));
            out[row0 + o + 1] = fmaxf(0.f, md0 * (acc[mi][n][1] + s01));
            out[row1 + o]     = fmaxf(0.f, md1 * (acc[mi][n][2] + s10));
            out[row1 + o + 1] = fmaxf(0.f, md1 * (acc[mi][n][3] + s11));
        }
    }
}

// ---------------------------------------------------------------------------
extern "C" void kernel_launch(void* const* d_in, const int* in_sizes, int n_in,
                              void* d_out, int out_size) {
    const float* H    = (const float*)d_in[0];
    const float* A    = (const float*)d_in[1];
    const float* mask = (const float*)d_in[2];
    const float* W    = (const float*)d_in[3];
    const float* bias = (const float*)d_in[4];
    float* out = (float*)d_out;

    cudaFuncSetAttribute(gemm1_mma, cudaFuncAttributeMaxDynamicSharedMemorySize, SMEM_TOTAL);
    cudaFuncSetAttribute(gemm2_mma, cudaFuncAttributeMaxDynamicSharedMemorySize, SMEM_TOTAL);

    prep_kernel<<<1088, 256>>>(A, H, W);
    gemm1_mma<<<dim3(128, 2), 256, SMEM_TOTAL>>>(bias);
    gemm2_mma<<<dim3(4, 2, B_), 256, SMEM_TOTAL>>>(mask, out);
}

// round 8
// speedup vs baseline: 1.2493x; 1.2493x over previous
#include <cuda_runtime.h>
#include <cuda_bf16.h>
#include <cstdint>

#define B_   32
#define N_   512
#define K1_  256
#define O_   256
#define EPSF 1e-8f

// ---- GEMM tiling: CTA 128m x 128n, KC=16, 256 threads (8 warps, 2x4) ------
#define KC      16
#define A_ROW   48                        // 16 bf16 + 12B pad (stride 48 = 3*16)
#define A_PLANE (128 * A_ROW)             // 6144
#define B_ROW   272                       // 128 bf16 + 16B pad (stride 17*16)
#define B_PLANE (KC * B_ROW)              // 4352
#define AUX_SZ  2048
#define STAGE   (2 * A_PLANE + 2 * B_PLANE)   // 20992
#define OFF_AH  0
#define OFF_AL  A_PLANE
#define OFF_BH  (2 * A_PLANE)
#define OFF_BL  (2 * A_PLANE + B_PLANE)
#define SMEM_TOTAL (AUX_SZ + 2 * STAGE)       // 44032 -> 2 CTAs/SM

#define BP_STEP ((KC * O_) / 4)               // uint4 units per K-chunk

// ---- scratch ----------------------------------------------------------------
__device__ __align__(16) float    g_dis[B_ * N_];
__device__ __align__(16) uint32_t g_HsP[B_ * N_ * O_];   // dis_j*(HW^T+b), packed bf16 hi|lo
__device__ __align__(16) uint32_t g_WtP[K1_ * O_];       // W^T packed bf16 hi|lo, [k][o]

// ---- helpers ------------------------------------------------------------------
__device__ __forceinline__ void ldsm_x4(uint32_t& r0, uint32_t& r1, uint32_t& r2,
                                        uint32_t& r3, uint32_t addr) {
    asm volatile("ldmatrix.sync.aligned.m8n8.x4.shared.b16 {%0,%1,%2,%3}, [%4];"
                 : "=r"(r0), "=r"(r1), "=r"(r2), "=r"(r3) : "r"(addr));
}
__device__ __forceinline__ void ldsm_x2t(uint32_t& r0, uint32_t& r1, uint32_t addr) {
    asm volatile("ldmatrix.sync.aligned.m8n8.x2.trans.shared.b16 {%0,%1}, [%2];"
                 : "=r"(r0), "=r"(r1) : "r"(addr));
}
__device__ __forceinline__ void mma16816(float* c,
                                         uint32_t a0, uint32_t a1, uint32_t a2, uint32_t a3,
                                         uint32_t b0, uint32_t b1) {
    asm volatile("mma.sync.aligned.m16n8k16.row.col.f32.bf16.bf16.f32 "
                 "{%0,%1,%2,%3}, {%4,%5,%6,%7}, {%8,%9}, {%0,%1,%2,%3};"
                 : "+f"(c[0]), "+f"(c[1]), "+f"(c[2]), "+f"(c[3])
                 : "r"(a0), "r"(a1), "r"(a2), "r"(a3), "r"(b0), "r"(b1));
}
__device__ __forceinline__ void split4(float4 f, uint2& hi, uint2& lo) {
    __nv_bfloat162 h01 = __floats2bfloat162_rn(f.x, f.y);
    __nv_bfloat162 h23 = __floats2bfloat162_rn(f.z, f.w);
    uint32_t u01 = *reinterpret_cast<uint32_t*>(&h01);
    uint32_t u23 = *reinterpret_cast<uint32_t*>(&h23);
    float r0 = f.x - __uint_as_float(u01 << 16);
    float r1 = f.y - __uint_as_float(u01 & 0xFFFF0000u);
    float r2 = f.z - __uint_as_float(u23 << 16);
    float r3 = f.w - __uint_as_float(u23 & 0xFFFF0000u);
    __nv_bfloat162 l01 = __floats2bfloat162_rn(r0, r1);
    __nv_bfloat162 l23 = __floats2bfloat162_rn(r2, r3);
    hi = make_uint2(u01, u23);
    lo = make_uint2(*reinterpret_cast<uint32_t*>(&l01), *reinterpret_cast<uint32_t*>(&l23));
}
__device__ __forceinline__ uint32_t packsplit(float v) {
    uint32_t hu = (uint32_t)__bfloat16_as_ushort(__float2bfloat16_rn(v));
    float r = v - __uint_as_float(hu << 16);
    uint32_t lu = (uint32_t)__bfloat16_as_ushort(__float2bfloat16_rn(r));
    return hu | (lu << 16);
}
__device__ __forceinline__ float unpacksplit(uint32_t q) {
    return __uint_as_float(q << 16) + __uint_as_float(q & 0xFFFF0000u);
}

// store A chunk slice (two consecutive float4 = 8 k) split into hi/lo planes
__device__ __forceinline__ void stconv_a(char* smem, uint32_t bufo, uint32_t soff,
                                         float4 a0, float4 a1) {
    uint2 h0, l0, h1, l1;
    split4(a0, h0, l0); split4(a1, h1, l1);
    *reinterpret_cast<uint4*>(smem + bufo + OFF_AH + soff) = make_uint4(h0.x, h0.y, h1.x, h1.y);
    *reinterpret_cast<uint4*>(smem + bufo + OFF_AL + soff) = make_uint4(l0.x, l0.y, l1.x, l1.y);
}
__device__ __forceinline__ void stconv_b(char* smem, uint32_t bufo, uint32_t soff,
                                         uint4 q0, uint4 q1) {
    uint4 hv, lv;
    hv.x = __byte_perm(q0.x, q0.y, 0x5410); hv.y = __byte_perm(q0.z, q0.w, 0x5410);
    hv.z = __byte_perm(q1.x, q1.y, 0x5410); hv.w = __byte_perm(q1.z, q1.w, 0x5410);
    lv.x = __byte_perm(q0.x, q0.y, 0x7632); lv.y = __byte_perm(q0.z, q0.w, 0x7632);
    lv.z = __byte_perm(q1.x, q1.y, 0x7632); lv.w = __byte_perm(q1.z, q1.w, 0x7632);
    *reinterpret_cast<uint4*>(smem + bufo + OFF_BH + soff) = hv;
    *reinterpret_cast<uint4*>(smem + bufo + OFF_BL + soff) = lv;
}

// per-chunk mma: 3 split terms in SEPARATED passes (no back-to-back same-acc RAW)
__device__ __forceinline__ void chunk_mma(float acc[4][4][4], uint32_t bufb,
                                          int wm, int wn, int lane) {
    const uint32_t arow = (uint32_t)((lane & 7) + ((lane >> 3) & 1) * 8);
    const uint32_t a_base = bufb + OFF_AH + (wm * 64 + arow) * A_ROW + (lane >> 4) * 16;
    const uint32_t b_base = bufb + OFF_BH + (lane & 15) * B_ROW + (wn * 32) * 2;

    uint32_t a[4][4], bh[4][2], bl[4][2];
#pragma unroll
    for (int mi = 0; mi < 4; mi++)
        ldsm_x4(a[mi][0], a[mi][1], a[mi][2], a[mi][3], a_base + mi * 16 * A_ROW);
#pragma unroll
    for (int n = 0; n < 4; n++) {
        ldsm_x2t(bh[n][0], bh[n][1], b_base + n * 16);
        ldsm_x2t(bl[n][0], bl[n][1], b_base + (OFF_BL - OFF_BH) + n * 16);
    }
    // pass 1: hi*hi — 16 independent accumulators
#pragma unroll
    for (int mi = 0; mi < 4; mi++)
#pragma unroll
        for (int n = 0; n < 4; n++)
            mma16816(acc[mi][n], a[mi][0], a[mi][1], a[mi][2], a[mi][3], bh[n][0], bh[n][1]);
    // pass 2: hi*lo — same acc 16 issues after pass 1 (latency hidden)
#pragma unroll
    for (int mi = 0; mi < 4; mi++)
#pragma unroll
        for (int n = 0; n < 4; n++)
            mma16816(acc[mi][n], a[mi][0], a[mi][1], a[mi][2], a[mi][3], bl[n][0], bl[n][1]);
    // reload A-lo (reuse regs), pass 3: lo*hi
#pragma unroll
    for (int mi = 0; mi < 4; mi++)
        ldsm_x4(a[mi][0], a[mi][1], a[mi][2], a[mi][3],
                a_base + (OFF_AL - OFF_AH) + mi * 16 * A_ROW);
#pragma unroll
    for (int mi = 0; mi < 4; mi++)
#pragma unroll
        for (int n = 0; n < 4; n++)
            mma16816(acc[mi][n], a[mi][0], a[mi][1], a[mi][2], a[mi][3], bh[n][0], bh[n][1]);
}

// ---------------------------------------------------------------------------
// prep: blocks [0,512): deg (32 rows each = all 16384); blocks [512,576): Wt.
// ---------------------------------------------------------------------------
#define DEG_BLKS 512
__global__ __launch_bounds__(256)
void prep_kernel(const float* __restrict__ A, const float* __restrict__ W) {
    __shared__ float tile[32][33];
    const int t = threadIdx.x;
    if (blockIdx.x < DEG_BLKS) {
        int wid = t >> 5, lane = t & 31;
        int row0 = (blockIdx.x * 8 + wid) * 4;
        const float4* a = reinterpret_cast<const float4*>(A + (size_t)row0 * N_);
        float s[4] = {0.f, 0.f, 0.f, 0.f};
#pragma unroll
        for (int c = 0; c < 4; c++)
#pragma unroll
            for (int r = 0; r < 4; r++) {
                float4 v = a[(size_t)r * 128 + lane + c * 32];
                s[r] += (v.x + v.y) + (v.z + v.w);
            }
#pragma unroll
        for (int o = 16; o > 0; o >>= 1)
#pragma unroll
            for (int r = 0; r < 4; r++) s[r] += __shfl_xor_sync(0xffffffffu, s[r], o);
        if (lane == 0)
#pragma unroll
            for (int r = 0; r < 4; r++) g_dis[row0 + r] = rsqrtf(s[r] + 1.0f + EPSF);
    } else {
        int idx = blockIdx.x - DEG_BLKS;       // 64 tiles: 8x8
        int k0 = (idx & 7) * 32, o0 = (idx >> 3) * 32;
        int tx = t & 31, ty = t >> 5;          // (32, 8)
#pragma unroll
        for (int i = 0; i < 32; i += 8)
            tile[ty + i][tx] = W[(size_t)(o0 + ty + i) * K1_ + k0 + tx];
        __syncthreads();
#pragma unroll
        for (int i = 0; i < 32; i += 8)
            g_WtP[(size_t)(k0 + ty + i) * O_ + o0 + tx] = packsplit(tile[tx][ty + i]);
    }
}

// ---------------------------------------------------------------------------
// GEMM1: Hs[m,o] = dis[m]*(sum_k H[m,k] W[o,k] + b[o]). CTA 128x128.
// grid (128 m-tiles, 2 o-tiles) = 256 CTAs, 2/SM.
// ---------------------------------------------------------------------------
__global__ __launch_bounds__(256, 2)
void gemm1_mma(const float* __restrict__ H, const float* __restrict__ bias) {
    extern __shared__ char smem[];
    const uint32_t sb = (uint32_t)__cvta_generic_to_shared(smem);
    const int t = threadIdx.x, lane = t & 31, wid = t >> 5;
    const int wm = wid >> 2, wn = wid & 3;
    const int bm = blockIdx.x * 128;
    const int bn = blockIdx.y * 128;

    float* bias_s = reinterpret_cast<float*>(smem);          // 128 f (this n-tile)
    float* dis_s  = reinterpret_cast<float*>(smem + 1024);   // 128 f
    if (t < 128) { bias_s[t] = bias[bn + t]; dis_s[t] = g_dis[bm + t]; }

    const int ar = t >> 1, ac = (t & 1) * 2;
    const float4* ap = reinterpret_cast<const float4*>(
        H + (size_t)(bm + ar) * K1_) + ac;
    const uint4* bp = reinterpret_cast<const uint4*>(
        g_WtP + (size_t)(t >> 4) * O_ + bn + (t & 15) * 8);
    const uint32_t a_soff = (uint32_t)(ar * A_ROW + ac * 8);
    const uint32_t b_soff = (uint32_t)((t >> 4) * B_ROW + (t & 15) * 16);

    float acc[4][4][4];
#pragma unroll
    for (int i = 0; i < 4; i++)
#pragma unroll
        for (int j = 0; j < 4; j++)
#pragma unroll
            for (int e = 0; e < 4; e++) acc[i][j][e] = 0.f;

    {
        float4 a0 = ap[0], a1 = ap[1]; uint4 q0 = bp[0], q1 = bp[1];
        ap += 4; bp += BP_STEP;
        stconv_a(smem, AUX_SZ, a_soff, a0, a1);
        stconv_b(smem, AUX_SZ, b_soff, q0, q1);
    }
    __syncthreads();

    const int S = K1_ / KC;  // 16
    for (int s = 0; s < S; s++) {
        float4 a0, a1; uint4 q0, q1;
        const bool pf = (s + 1 < S);
        if (pf) { a0 = ap[0]; a1 = ap[1]; q0 = bp[0]; q1 = bp[1]; ap += 4; bp += BP_STEP; }
        chunk_mma(acc, sb + AUX_SZ + (uint32_t)(s & 1) * STAGE, wm, wn, lane);
        if (pf) {
            uint32_t bo = AUX_SZ + (uint32_t)((s + 1) & 1) * STAGE;
            stconv_a(smem, bo, a_soff, a0, a1);
            stconv_b(smem, bo, b_soff, q0, q1);
        }
        __syncthreads();
    }

    const int g = lane >> 2, i4 = lane & 3;
#pragma unroll
    for (int mi = 0; mi < 4; mi++) {
        int r0 = wm * 64 + mi * 16 + g;
        float d0 = dis_s[r0], d1 = dis_s[r0 + 8];
        uint32_t* dst0 = g_HsP + (size_t)(bm + r0) * O_ + bn;
        uint32_t* dst1 = dst0 + 8 * O_;
#pragma unroll
        for (int n = 0; n < 4; n++) {
            int o = wn * 32 + n * 8 + i4 * 2;
            float b0 = bias_s[o], b1 = bias_s[o + 1];
            dst0[o]     = packsplit((acc[mi][n][0] + b0) * d0);
            dst0[o + 1] = packsplit((acc[mi][n][1] + b1) * d0);
            dst1[o]     = packsplit((acc[mi][n][2] + b0) * d1);
            dst1[o + 1] = packsplit((acc[mi][n][3] + b1) * d1);
        }
    }
}

// ---------------------------------------------------------------------------
// GEMM2: out[b,i,o] = relu(mask*dis_i*(sum_j A[i,j] Hs[j,o] + Hs[i,o])).
// CTA 128x128, grid (4 i-tiles, 2 o-tiles, 32 b) = 256 CTAs, 2/SM.
// ---------------------------------------------------------------------------
__global__ __launch_bounds__(256, 2)
void gemm2_mma(const float* __restrict__ A, const float* __restrict__ mask,
               float* __restrict__ out) {
    extern __shared__ char smem[];
    const uint32_t sb = (uint32_t)__cvta_generic_to_shared(smem);
    const int t = threadIdx.x, lane = t & 31, wid = t >> 5;
    const int wm = wid >> 2, wn = wid & 3;
    const int i0 = blockIdx.x * 128;
    const int bn = blockIdx.y * 128;
    const int b  = blockIdx.z;

    float* mdis_s = reinterpret_cast<float*>(smem);   // 128 f
    if (t < 128) mdis_s[t] = mask[b * N_ + i0 + t] * g_dis[b * N_ + i0 + t];

    const int ar = t >> 1, ac = (t & 1) * 2;
    const float4* ap = reinterpret_cast<const float4*>(
        A + ((size_t)b * N_ + i0 + ar) * N_) + ac;
    const uint4* bp = reinterpret_cast<const uint4*>(
        g_HsP + (size_t)b * N_ * O_ + (size_t)(t >> 4) * O_ + bn + (t & 15) * 8);
    const uint32_t a_soff = (uint32_t)(ar * A_ROW + ac * 8);
    const uint32_t b_soff = (uint32_t)((t >> 4) * B_ROW + (t & 15) * 16);

    float acc[4][4][4];
#pragma unroll
    for (int i = 0; i < 4; i++)
#pragma unroll
        for (int j = 0; j < 4; j++)
#pragma unroll
            for (int e = 0; e < 4; e++) acc[i][j][e] = 0.f;

    {
        float4 a0 = ap[0], a1 = ap[1]; uint4 q0 = bp[0], q1 = bp[1];
        ap += 4; bp += BP_STEP;
        stconv_a(smem, AUX_SZ, a_soff, a0, a1);
        stconv_b(smem, AUX_SZ, b_soff, q0, q1);
    }
    __syncthreads();

    const int S = N_ / KC;  // 32
    for (int s = 0; s < S; s++) {
        float4 a0, a1; uint4 q0, q1;
        const bool pf = (s + 1 < S);
        if (pf) { a0 = ap[0]; a1 = ap[1]; q0 = bp[0]; q1 = bp[1]; ap += 4; bp += BP_STEP; }
        chunk_mma(acc, sb + AUX_SZ + (uint32_t)(s & 1) * STAGE, wm, wn, lane);
        if (pf) {
            uint32_t bo = AUX_SZ + (uint32_t)((s + 1) & 1) * STAGE;
            stconv_a(smem, bo, a_soff, a0, a1);
            stconv_b(smem, bo, b_soff, q0, q1);
        }
        __syncthreads();
    }

    const int g = lane >> 2, i4 = lane & 3;
#pragma unroll
    for (int mi = 0; mi < 4; mi++) {
        int r0 = wm * 64 + mi * 16 + g;
        float md0 = mdis_s[r0], md1 = mdis_s[r0 + 8];
        size_t row0 = ((size_t)b * N_ + i0 + r0) * O_ + bn;
        size_t row1 = row0 + 8 * O_;
#pragma unroll
        for (int n = 0; n < 4; n++) {
            int o = wn * 32 + n * 8 + i4 * 2;
            float s00 = unpacksplit(g_HsP[row0 + o]);
            float s01 = unpacksplit(g_HsP[row0 + o + 1]);
            float s10 = unpacksplit(g_HsP[row1 + o]);
            float s11 = unpacksplit(g_HsP[row1 + o + 1]);
            out[row0 + o]     = fmaxf(0.f, md0 * (acc[mi][n][0] + s00));
            out[row0 + o + 1] = fmaxf(0.f, md0 * (acc[mi][n][1] + s01));
            out[row1 + o]     = fmaxf(0.f, md1 * (acc[mi][n][2] + s10));
            out[row1 + o + 1] = fmaxf(0.f, md1 * (acc[mi][n][3] + s11));
        }
    }
}

// ---------------------------------------------------------------------------
extern "C" void kernel_launch(void* const* d_in, const int* in_sizes, int n_in,
                              void* d_out, int out_size) {
    const float* H    = (const float*)d_in[0];
    const float* A    = (const float*)d_in[1];
    const float* mask = (const float*)d_in[2];
    const float* W    = (const float*)d_in[3];
    const float* bias = (const float*)d_in[4];
    float* out = (float*)d_out;

    cudaFuncSetAttribute(gemm1_mma, cudaFuncAttributeMaxDynamicSharedMemorySize, SMEM_TOTAL);
    cudaFuncSetAttribute(gemm2_mma, cudaFuncAttributeMaxDynamicSharedMemorySize, SMEM_TOTAL);

    prep_kernel<<<DEG_BLKS + 64, 256>>>(A, W);
    gemm1_mma<<<dim3(128, 2), 256, SMEM_TOTAL>>>(H, bias);
    gemm2_mma<<<dim3(4, 2, B_), 256, SMEM_TOTAL>>>(A, mask, out);
}

// round 9
// speedup vs baseline: 2.0245x; 1.6205x over previous
#include <cuda_runtime.h>
#include <cuda_fp16.h>
#include <cstdint>

#define B_   32
#define N_   512
#define K1_  256
#define O_   256
#define EPSF 1e-8f

// ---- GEMM tiling: CTA 128m x 128n, KC=16, 256 threads (8 warps, 2x4) ------
#define KC      16
#define A_ROW   48                        // 16 fp16 (32B) + 16B pad
#define A_PLANE (128 * A_ROW)             // 6144
#define B_ROW   272                       // 128 fp16 (256B) + 16B pad
#define B_PLANE (KC * B_ROW)              // 4352
#define AUX_SZ  2048
#define STAGE   (A_PLANE + B_PLANE)       // 10496
#define OFF_A   0
#define OFF_B   A_PLANE
#define SMEM_TOTAL (AUX_SZ + 2 * STAGE)   // 23040

// ---- scratch ----------------------------------------------------------------
__device__ __align__(16) float    g_dis[B_ * N_];
__device__ __align__(16) uint32_t g_HsH[B_ * N_ * O_ / 2];  // Hs fp16 pairs [b][j][o]
__device__ __align__(16) uint32_t g_WtH[K1_ * O_ / 2];      // W^T fp16 pairs [k][o]

// ---- helpers ------------------------------------------------------------------
__device__ __forceinline__ void ldsm_x4(uint32_t& r0, uint32_t& r1, uint32_t& r2,
                                        uint32_t& r3, uint32_t addr) {
    asm volatile("ldmatrix.sync.aligned.m8n8.x4.shared.b16 {%0,%1,%2,%3}, [%4];"
                 : "=r"(r0), "=r"(r1), "=r"(r2), "=r"(r3) : "r"(addr));
}
__device__ __forceinline__ void ldsm_x2t(uint32_t& r0, uint32_t& r1, uint32_t addr) {
    asm volatile("ldmatrix.sync.aligned.m8n8.x2.trans.shared.b16 {%0,%1}, [%2];"
                 : "=r"(r0), "=r"(r1) : "r"(addr));
}
__device__ __forceinline__ void mma16816(float* c,
                                         uint32_t a0, uint32_t a1, uint32_t a2, uint32_t a3,
                                         uint32_t b0, uint32_t b1) {
    asm volatile("mma.sync.aligned.m16n8k16.row.col.f32.f16.f16.f32 "
                 "{%0,%1,%2,%3}, {%4,%5,%6,%7}, {%8,%9}, {%0,%1,%2,%3};"
                 : "+f"(c[0]), "+f"(c[1]), "+f"(c[2]), "+f"(c[3])
                 : "r"(a0), "r"(a1), "r"(a2), "r"(a3), "r"(b0), "r"(b1));
}
__device__ __forceinline__ uint32_t packh2(float v0, float v1) {
    __half2 h = __floats2half2_rn(v0, v1);
    return *reinterpret_cast<uint32_t*>(&h);
}
__device__ __forceinline__ float2 unpackh2(uint32_t q) {
    __half2 h = *reinterpret_cast<__half2*>(&q);
    return __half22float2(h);
}

// A chunk slice: two float4 (8 fp32 k-values) -> 8 fp16 -> one uint4
__device__ __forceinline__ void stconv_a(char* smem, uint32_t bufo, uint32_t soff,
                                         float4 a0, float4 a1) {
    uint4 v;
    v.x = packh2(a0.x, a0.y); v.y = packh2(a0.z, a0.w);
    v.z = packh2(a1.x, a1.y); v.w = packh2(a1.z, a1.w);
    *reinterpret_cast<uint4*>(smem + bufo + OFF_A + soff) = v;
}

// per-chunk mma: single fp16 pass, warp tile 64x32
__device__ __forceinline__ void chunk_mma(float acc[4][4][4], uint32_t bufb,
                                          int wm, int wn, int lane) {
    const uint32_t arow = (uint32_t)((lane & 7) + ((lane >> 3) & 1) * 8);
    const uint32_t a_base = bufb + OFF_A + (wm * 64 + arow) * A_ROW + (lane >> 4) * 16;
    const uint32_t b_base = bufb + OFF_B + (lane & 15) * B_ROW + (wn * 32) * 2;

    uint32_t a[4][4], bb[4][2];
#pragma unroll
    for (int mi = 0; mi < 4; mi++)
        ldsm_x4(a[mi][0], a[mi][1], a[mi][2], a[mi][3], a_base + mi * 16 * A_ROW);
#pragma unroll
    for (int n = 0; n < 4; n++)
        ldsm_x2t(bb[n][0], bb[n][1], b_base + n * 16);
#pragma unroll
    for (int mi = 0; mi < 4; mi++)
#pragma unroll
        for (int n = 0; n < 4; n++)
            mma16816(acc[mi][n], a[mi][0], a[mi][1], a[mi][2], a[mi][3], bb[n][0], bb[n][1]);
}

// ---------------------------------------------------------------------------
// prep: blocks [0,512): deg (32 rows each); blocks [512,576): W^T fp16.
// ---------------------------------------------------------------------------
#define DEG_BLKS 512
__global__ __launch_bounds__(256)
void prep_kernel(const float* __restrict__ A, const float* __restrict__ W) {
    __shared__ float tile[32][33];
    const int t = threadIdx.x;
    if (blockIdx.x < DEG_BLKS) {
        int wid = t >> 5, lane = t & 31;
        int row0 = (blockIdx.x * 8 + wid) * 4;
        const float4* a = reinterpret_cast<const float4*>(A + (size_t)row0 * N_);
        float s[4] = {0.f, 0.f, 0.f, 0.f};
#pragma unroll
        for (int c = 0; c < 4; c++)
#pragma unroll
            for (int r = 0; r < 4; r++) {
                float4 v = a[(size_t)r * 128 + lane + c * 32];
                s[r] += (v.x + v.y) + (v.z + v.w);
            }
#pragma unroll
        for (int o = 16; o > 0; o >>= 1)
#pragma unroll
            for (int r = 0; r < 4; r++) s[r] += __shfl_xor_sync(0xffffffffu, s[r], o);
        if (lane == 0)
#pragma unroll
            for (int r = 0; r < 4; r++) g_dis[row0 + r] = rsqrtf(s[r] + 1.0f + EPSF);
    } else {
        int idx = blockIdx.x - DEG_BLKS;       // 64 tiles: 8x8
        int k0 = (idx & 7) * 32, o0 = (idx >> 3) * 32;
        int tx = t & 31, ty = t >> 5;          // (32, 8)
#pragma unroll
        for (int i = 0; i < 32; i += 8)
            tile[ty + i][tx] = W[(size_t)(o0 + ty + i) * K1_ + k0 + tx];
        __syncthreads();
        int txp = t & 15, typ = t >> 4;        // (16, 16)
#pragma unroll
        for (int i = 0; i < 32; i += 16) {
            int k = typ + i;
            g_WtH[((size_t)(k0 + k) * O_ + o0 + txp * 2) >> 1] =
                packh2(tile[txp * 2][k], tile[txp * 2 + 1][k]);
        }
    }
}

// ---------------------------------------------------------------------------
// GEMM1: Hs[m,o] = dis[m]*(sum_k H[m,k] W[o,k] + b[o]); write Hs fp16 pairs.
// CTA 128x128, grid (128, 2).
// ---------------------------------------------------------------------------
__global__ __launch_bounds__(256, 2)
void gemm1_mma(const float* __restrict__ H, const float* __restrict__ bias) {
    extern __shared__ char smem[];
    const uint32_t sb = (uint32_t)__cvta_generic_to_shared(smem);
    const int t = threadIdx.x, lane = t & 31, wid = t >> 5;
    const int wm = wid >> 2, wn = wid & 3;
    const int bm = blockIdx.x * 128;
    const int bn = blockIdx.y * 128;

    float* bias_s = reinterpret_cast<float*>(smem);
    float* dis_s  = reinterpret_cast<float*>(smem + 1024);
    if (t < 128) { bias_s[t] = bias[bn + t]; dis_s[t] = g_dis[bm + t]; }

    const int ar = t >> 1, ac = (t & 1) * 2;
    const float4* ap = reinterpret_cast<const float4*>(
        H + (size_t)(bm + ar) * K1_) + ac;
    const char* bsrc = reinterpret_cast<const char*>(g_WtH)
                     + (size_t)(t >> 4) * 512 + (size_t)bn * 2 + (t & 15) * 16;
    const uint32_t a_soff = (uint32_t)(ar * A_ROW + ac * 8);
    const uint32_t b_soff = (uint32_t)((t >> 4) * B_ROW + (t & 15) * 16);

    float acc[4][4][4];
#pragma unroll
    for (int i = 0; i < 4; i++)
#pragma unroll
        for (int j = 0; j < 4; j++)
#pragma unroll
            for (int e = 0; e < 4; e++) acc[i][j][e] = 0.f;

    {
        float4 a0 = ap[0], a1 = ap[1];
        uint4 q = *reinterpret_cast<const uint4*>(bsrc);
        ap += 4; bsrc += 8192;
        stconv_a(smem, AUX_SZ, a_soff, a0, a1);
        *reinterpret_cast<uint4*>(smem + AUX_SZ + OFF_B + b_soff) = q;
    }
    __syncthreads();

    const int S = K1_ / KC;  // 16
    for (int s = 0; s < S; s++) {
        float4 a0, a1; uint4 q;
        const bool pf = (s + 1 < S);
        if (pf) { a0 = ap[0]; a1 = ap[1]; q = *reinterpret_cast<const uint4*>(bsrc);
                  ap += 4; bsrc += 8192; }
        chunk_mma(acc, sb + AUX_SZ + (uint32_t)(s & 1) * STAGE, wm, wn, lane);
        if (pf) {
            uint32_t bo = AUX_SZ + (uint32_t)((s + 1) & 1) * STAGE;
            stconv_a(smem, bo, a_soff, a0, a1);
            *reinterpret_cast<uint4*>(smem + bo + OFF_B + b_soff) = q;
        }
        __syncthreads();
    }

    // epilogue: +bias, *dis, fp16 pairs to g_HsH
    const int g = lane >> 2, i4 = lane & 3;
#pragma unroll
    for (int mi = 0; mi < 4; mi++) {
        int r0 = wm * 64 + mi * 16 + g;
        float d0 = dis_s[r0], d1 = dis_s[r0 + 8];
        size_t base0 = (size_t)(bm + r0) * O_ + bn;
        size_t base1 = base0 + 8 * O_;
#pragma unroll
        for (int n = 0; n < 4; n++) {
            int o = wn * 32 + n * 8 + i4 * 2;
            float b0 = bias_s[o], b1 = bias_s[o + 1];
            g_HsH[(base0 + o) >> 1] = packh2((acc[mi][n][0] + b0) * d0,
                                             (acc[mi][n][1] + b1) * d0);
            g_HsH[(base1 + o) >> 1] = packh2((acc[mi][n][2] + b0) * d1,
                                             (acc[mi][n][3] + b1) * d1);
        }
    }
}

// ---------------------------------------------------------------------------
// GEMM2: out[b,i,o] = relu(mask*dis_i*(sum_j A[i,j] Hs[j,o] + Hs[i,o])).
// CTA 128x128, grid (4, 2, 32).
// ---------------------------------------------------------------------------
__global__ __launch_bounds__(256, 2)
void gemm2_mma(const float* __restrict__ A, const float* __restrict__ mask,
               float* __restrict__ out) {
    extern __shared__ char smem[];
    const uint32_t sb = (uint32_t)__cvta_generic_to_shared(smem);
    const int t = threadIdx.x, lane = t & 31, wid = t >> 5;
    const int wm = wid >> 2, wn = wid & 3;
    const int i0 = blockIdx.x * 128;
    const int bn = blockIdx.y * 128;
    const int b  = blockIdx.z;

    float* mdis_s = reinterpret_cast<float*>(smem);
    if (t < 128) mdis_s[t] = mask[b * N_ + i0 + t] * g_dis[b * N_ + i0 + t];

    const int ar = t >> 1, ac = (t & 1) * 2;
    const float4* ap = reinterpret_cast<const float4*>(
        A + ((size_t)b * N_ + i0 + ar) * N_) + ac;
    const char* bsrc = reinterpret_cast<const char*>(g_HsH)
                     + ((size_t)b * N_ + (t >> 4)) * 512 + (size_t)bn * 2 + (t & 15) * 16;
    const uint32_t a_soff = (uint32_t)(ar * A_ROW + ac * 8);
    const uint32_t b_soff = (uint32_t)((t >> 4) * B_ROW + (t & 15) * 16);

    float acc[4][4][4];
#pragma unroll
    for (int i = 0; i < 4; i++)
#pragma unroll
        for (int j = 0; j < 4; j++)
#pragma unroll
            for (int e = 0; e < 4; e++) acc[i][j][e] = 0.f;

    {
        float4 a0 = ap[0], a1 = ap[1];
        uint4 q = *reinterpret_cast<const uint4*>(bsrc);
        ap += 4; bsrc += 8192;
        stconv_a(smem, AUX_SZ, a_soff, a0, a1);
        *reinterpret_cast<uint4*>(smem + AUX_SZ + OFF_B + b_soff) = q;
    }
    __syncthreads();

    const int S = N_ / KC;  // 32
    for (int s = 0; s < S; s++) {
        float4 a0, a1; uint4 q;
        const bool pf = (s + 1 < S);
        if (pf) { a0 = ap[0]; a1 = ap[1]; q = *reinterpret_cast<const uint4*>(bsrc);
                  ap += 4; bsrc += 8192; }
        chunk_mma(acc, sb + AUX_SZ + (uint32_t)(s & 1) * STAGE, wm, wn, lane);
        if (pf) {
            uint32_t bo = AUX_SZ + (uint32_t)((s + 1) & 1) * STAGE;
            stconv_a(smem, bo, a_soff, a0, a1);
            *reinterpret_cast<uint4*>(smem + bo + OFF_B + b_soff) = q;
        }
        __syncthreads();
    }

    // epilogue: + self-loop Hs[i,o] (fp16), * mask*dis_i, relu
    const int g = lane >> 2, i4 = lane & 3;
#pragma unroll
    for (int mi = 0; mi < 4; mi++) {
        int r0 = wm * 64 + mi * 16 + g;
        float md0 = mdis_s[r0], md1 = mdis_s[r0 + 8];
        size_t row0 = ((size_t)b * N_ + i0 + r0) * O_ + bn;
        size_t row1 = row0 + 8 * O_;
#pragma unroll
        for (int n = 0; n < 4; n++) {
            int o = wn * 32 + n * 8 + i4 * 2;
            float2 s0 = unpackh2(g_HsH[(row0 + o) >> 1]);
            float2 s1 = unpackh2(g_HsH[(row1 + o) >> 1]);
            out[row0 + o]     = fmaxf(0.f, md0 * (acc[mi][n][0] + s0.x));
            out[row0 + o + 1] = fmaxf(0.f, md0 * (acc[mi][n][1] + s0.y));
            out[row1 + o]     = fmaxf(0.f, md1 * (acc[mi][n][2] + s1.x));
            out[row1 + o + 1] = fmaxf(0.f, md1 * (acc[mi][n][3] + s1.y));
        }
    }
}

// ---------------------------------------------------------------------------
extern "C" void kernel_launch(void* const* d_in, const int* in_sizes, int n_in,
                              void* d_out, int out_size) {
    const float* H    = (const float*)d_in[0];
    const float* A    = (const float*)d_in[1];
    const float* mask = (const float*)d_in[2];
    const float* W    = (const float*)d_in[3];
    const float* bias = (const float*)d_in[4];
    float* out = (float*)d_out;

    cudaFuncSetAttribute(gemm1_mma, cudaFuncAttributeMaxDynamicSharedMemorySize, SMEM_TOTAL);
    cudaFuncSetAttribute(gemm2_mma, cudaFuncAttributeMaxDynamicSharedMemorySize, SMEM_TOTAL);

    prep_kernel<<<DEG_BLKS + 64, 256>>>(A, W);
    gemm1_mma<<<dim3(128, 2), 256, SMEM_TOTAL>>>(H, bias);
    gemm2_mma<<<dim3(4, 2, B_), 256, SMEM_TOTAL>>>(A, mask, out);
}

// round 10
// speedup vs baseline: 2.1116x; 1.0430x over previous
#include <cuda_runtime.h>
#include <cuda_fp16.h>
#include <cstdint>

#define B_   32
#define N_   512
#define K1_  256
#define O_   256
#define EPSF 1e-8f

// ---- GEMM tiling: CTA 128m x 128n, KC=32, 256 threads, 4-stage cp.async ----
#define KC      32
#define A_ROW   80                        // 32 fp16 (64B) + 16B pad
#define A_PLANE (128 * A_ROW)             // 10240
#define B_ROW   272                       // 128 fp16 (256B) + 16B pad
#define B_PLANE (KC * B_ROW)              // 8704
#define AUX_SZ  2048
#define STAGE   (A_PLANE + B_PLANE)       // 18944
#define OFF_A   0
#define OFF_B   A_PLANE
#define NSTAGE  4
#define SMEM_TOTAL (AUX_SZ + NSTAGE * STAGE)   // 77824 -> 2 CTAs/SM (152KB)

// ---- scratch: all operands pre-converted to fp16 in prep -------------------
__device__ __align__(16) float    g_dis[B_ * N_];
__device__ __align__(16) uint32_t g_A16[B_ * N_ * N_ / 2];   // A fp16 [b][i][j]
__device__ __align__(16) uint32_t g_H16[B_ * N_ * K1_ / 2];  // H fp16 [m][k]
__device__ __align__(16) uint32_t g_HsH[B_ * N_ * O_ / 2];   // Hs fp16 [b][j][o]
__device__ __align__(16) uint32_t g_WtH[K1_ * O_ / 2];       // W^T fp16 [k][o]

// ---- helpers ----------------------------------------------------------------
__device__ __forceinline__ void ldsm_x4(uint32_t& r0, uint32_t& r1, uint32_t& r2,
                                        uint32_t& r3, uint32_t addr) {
    asm volatile("ldmatrix.sync.aligned.m8n8.x4.shared.b16 {%0,%1,%2,%3}, [%4];"
                 : "=r"(r0), "=r"(r1), "=r"(r2), "=r"(r3) : "r"(addr));
}
__device__ __forceinline__ void ldsm_x4t(uint32_t& r0, uint32_t& r1, uint32_t& r2,
                                         uint32_t& r3, uint32_t addr) {
    asm volatile("ldmatrix.sync.aligned.m8n8.x4.trans.shared.b16 {%0,%1,%2,%3}, [%4];"
                 : "=r"(r0), "=r"(r1), "=r"(r2), "=r"(r3) : "r"(addr));
}
__device__ __forceinline__ void mma16816(float* c,
                                         uint32_t a0, uint32_t a1, uint32_t a2, uint32_t a3,
                                         uint32_t b0, uint32_t b1) {
    asm volatile("mma.sync.aligned.m16n8k16.row.col.f32.f16.f16.f32 "
                 "{%0,%1,%2,%3}, {%4,%5,%6,%7}, {%8,%9}, {%0,%1,%2,%3};"
                 : "+f"(c[0]), "+f"(c[1]), "+f"(c[2]), "+f"(c[3])
                 : "r"(a0), "r"(a1), "r"(a2), "r"(a3), "r"(b0), "r"(b1));
}
__device__ __forceinline__ uint32_t packh2(float v0, float v1) {
    __half2 h = __floats2half2_rn(v0, v1);
    return *reinterpret_cast<uint32_t*>(&h);
}
__device__ __forceinline__ float2 unpackh2(uint32_t q) {
    __half2 h = *reinterpret_cast<__half2*>(&q);
    return __half22float2(h);
}
__device__ __forceinline__ void cpa16(uint32_t dst, const void* src) {
    asm volatile("cp.async.cg.shared.global [%0], [%1], 16;" :: "r"(dst), "l"(src));
}
#define CP_COMMIT() asm volatile("cp.async.commit_group;" ::: "memory")
#define CP_WAIT(n)  asm volatile("cp.async.wait_group %0;" :: "n"(n) : "memory")

// per-chunk mma: KC=32 (2 k-halves of 16), warp tile 64x32
__device__ __forceinline__ void chunk_mma32(float acc[4][4][4], uint32_t bufb,
                                            int wm, int wn, int lane) {
    const uint32_t arow = (uint32_t)((lane & 7) + ((lane >> 3) & 1) * 8);
#pragma unroll
    for (int kh = 0; kh < 2; kh++) {
        const uint32_t a_base = bufb + OFF_A + (wm * 64 + arow) * A_ROW
                              + kh * 32 + (lane >> 4) * 16;
        uint32_t a[4][4], bb[4][2];
#pragma unroll
        for (int mi = 0; mi < 4; mi++)
            ldsm_x4(a[mi][0], a[mi][1], a[mi][2], a[mi][3], a_base + mi * 16 * A_ROW);
#pragma unroll
        for (int p = 0; p < 2; p++) {
            const uint32_t baddr = bufb + OFF_B + (kh * 16 + (lane & 15)) * B_ROW
                                 + (wn * 32 + p * 16 + (lane >> 4) * 8) * 2;
            ldsm_x4t(bb[2 * p][0], bb[2 * p][1], bb[2 * p + 1][0], bb[2 * p + 1][1], baddr);
        }
#pragma unroll
        for (int mi = 0; mi < 4; mi++)
#pragma unroll
            for (int n = 0; n < 4; n++)
                mma16816(acc[mi][n], a[mi][0], a[mi][1], a[mi][2], a[mi][3],
                         bb[n][0], bb[n][1]);
    }
}

// ---------------------------------------------------------------------------
// prep: [0,512): A -> deg + A16; [512,768): H -> H16; [768,832): W^T fp16.
// ---------------------------------------------------------------------------
__global__ __launch_bounds__(256)
void prep_kernel(const float* __restrict__ A, const float* __restrict__ H,
                 const float* __restrict__ W) {
    __shared__ float tile[32][33];
    const int t = threadIdx.x;
    if (blockIdx.x < 512) {
        int wid = t >> 5, lane = t & 31;
        int row0 = (blockIdx.x * 8 + wid) * 4;
        const float4* a = reinterpret_cast<const float4*>(A + (size_t)row0 * N_);
        uint2* a16 = reinterpret_cast<uint2*>(g_A16);
        float s[4] = {0.f, 0.f, 0.f, 0.f};
#pragma unroll
        for (int c = 0; c < 4; c++)
#pragma unroll
            for (int r = 0; r < 4; r++) {
                float4 v = a[(size_t)r * 128 + lane + c * 32];
                s[r] += (v.x + v.y) + (v.z + v.w);
                a16[(size_t)(row0 + r) * 128 + lane + c * 32] =
                    make_uint2(packh2(v.x, v.y), packh2(v.z, v.w));
            }
#pragma unroll
        for (int o = 16; o > 0; o >>= 1)
#pragma unroll
            for (int r = 0; r < 4; r++) s[r] += __shfl_xor_sync(0xffffffffu, s[r], o);
        if (lane == 0)
#pragma unroll
            for (int r = 0; r < 4; r++) g_dis[row0 + r] = rsqrtf(s[r] + 1.0f + EPSF);
    } else if (blockIdx.x < 768) {
        int hb = blockIdx.x - 512;             // 64 H rows per block
        const float4* h4 = reinterpret_cast<const float4*>(H) + (size_t)hb * 4096;
        uint4* h16 = reinterpret_cast<uint4*>(g_H16) + (size_t)hb * 2048;
#pragma unroll
        for (int it = 0; it < 8; it++) {
            int gidx = t + it * 256;
            float4 f0 = h4[2 * gidx], f1 = h4[2 * gidx + 1];
            h16[gidx] = make_uint4(packh2(f0.x, f0.y), packh2(f0.z, f0.w),
                                   packh2(f1.x, f1.y), packh2(f1.z, f1.w));
        }
    } else {
        int idx = blockIdx.x - 768;            // 64 tiles: 8x8
        int k0 = (idx & 7) * 32, o0 = (idx >> 3) * 32;
        int tx = t & 31, ty = t >> 5;          // (32, 8)
#pragma unroll
        for (int i = 0; i < 32; i += 8)
            tile[ty + i][tx] = W[(size_t)(o0 + ty + i) * K1_ + k0 + tx];
        __syncthreads();
        int txp = t & 15, typ = t >> 4;        // (16, 16)
#pragma unroll
        for (int i = 0; i < 32; i += 16) {
            int k = typ + i;
            g_WtH[((size_t)(k0 + k) * O_ + o0 + txp * 2) >> 1] =
                packh2(tile[txp * 2][k], tile[txp * 2 + 1][k]);
        }
    }
}

// ---------------------------------------------------------------------------
// GEMM1: Hs[m,o] = dis[m]*(sum_k H[m,k] W[o,k] + b[o]); fp16, 4-stage cp.async.
// CTA 128x128, grid (128, 2). K=256 -> 8 chunks of 32.
// ---------------------------------------------------------------------------
__global__ __launch_bounds__(256, 2)
void gemm1_mma(const float* __restrict__ bias) {
    extern __shared__ char smem[];
    const uint32_t sb = (uint32_t)__cvta_generic_to_shared(smem);
    const int t = threadIdx.x, lane = t & 31, wid = t >> 5;
    const int wm = wid >> 2, wn = wid & 3;
    const int bm = blockIdx.x * 128;
    const int bn = blockIdx.y * 128;

    float* bias_s = reinterpret_cast<float*>(smem);
    float* dis_s  = reinterpret_cast<float*>(smem + 1024);
    if (t < 128) { bias_s[t] = bias[bn + t]; dis_s[t] = g_dis[bm + t]; }

    const char* srcA = reinterpret_cast<const char*>(g_H16)
                     + (size_t)(bm + (t >> 1)) * 512 + (t & 1) * 32;
    const char* srcB = reinterpret_cast<const char*>(g_WtH)
                     + (size_t)(t >> 4) * 512 + (size_t)bn * 2 + (t & 15) * 16;
    const uint32_t soa = sb + AUX_SZ + OFF_A + (t >> 1) * A_ROW + (t & 1) * 32;
    const uint32_t sob = sb + AUX_SZ + OFF_B + (t >> 4) * B_ROW + (t & 15) * 16;

    auto issue = [&](int s, uint32_t buf) {
        uint32_t st = buf * STAGE;
        cpa16(soa + st,      srcA + s * 64);
        cpa16(soa + st + 16, srcA + s * 64 + 16);
        cpa16(sob + st,            srcB + (size_t)s * 16384);
        cpa16(sob + st + 16 * B_ROW, srcB + (size_t)s * 16384 + 16 * 512);
    };

    float acc[4][4][4];
#pragma unroll
    for (int i = 0; i < 4; i++)
#pragma unroll
        for (int j = 0; j < 4; j++)
#pragma unroll
            for (int e = 0; e < 4; e++) acc[i][j][e] = 0.f;

    const int S = K1_ / KC;  // 8
#pragma unroll
    for (int p = 0; p < 3; p++) { issue(p, p); CP_COMMIT(); }

    for (int s = 0; s < S; s++) {
        CP_WAIT(2);
        __syncthreads();
        if (s + 3 < S) issue(s + 3, (uint32_t)((s + 3) & 3));
        CP_COMMIT();
        chunk_mma32(acc, sb + AUX_SZ + (uint32_t)(s & 3) * STAGE, wm, wn, lane);
    }

    // epilogue: +bias, *dis, fp16 pairs to g_HsH
    const int g = lane >> 2, i4 = lane & 3;
#pragma unroll
    for (int mi = 0; mi < 4; mi++) {
        int r0 = wm * 64 + mi * 16 + g;
        float d0 = dis_s[r0], d1 = dis_s[r0 + 8];
        size_t base0 = (size_t)(bm + r0) * O_ + bn;
        size_t base1 = base0 + 8 * O_;
#pragma unroll
        for (int n = 0; n < 4; n++) {
            int o = wn * 32 + n * 8 + i4 * 2;
            g_HsH[(base0 + o) >> 1] = packh2((acc[mi][n][0] + bias_s[o]) * d0,
                                             (acc[mi][n][1] + bias_s[o + 1]) * d0);
            g_HsH[(base1 + o) >> 1] = packh2((acc[mi][n][2] + bias_s[o]) * d1,
                                             (acc[mi][n][3] + bias_s[o + 1]) * d1);
        }
    }
}

// ---------------------------------------------------------------------------
// GEMM2: out[b,i,o] = relu(mask*dis_i*(sum_j A[i,j] Hs[j,o] + Hs[i,o])).
// CTA 128x128, grid (4, 2, 32). K=512 -> 16 chunks of 32.
// ---------------------------------------------------------------------------
__global__ __launch_bounds__(256, 2)
void gemm2_mma(const float* __restrict__ mask, float* __restrict__ out) {
    extern __shared__ char smem[];
    const uint32_t sb = (uint32_t)__cvta_generic_to_shared(smem);
    const int t = threadIdx.x, lane = t & 31, wid = t >> 5;
    const int wm = wid >> 2, wn = wid & 3;
    const int i0 = blockIdx.x * 128;
    const int bn = blockIdx.y * 128;
    const int b  = blockIdx.z;

    float* mdis_s = reinterpret_cast<float*>(smem);
    if (t < 128) mdis_s[t] = mask[b * N_ + i0 + t] * g_dis[b * N_ + i0 + t];

    const char* srcA = reinterpret_cast<const char*>(g_A16)
                     + ((size_t)b * N_ + i0 + (t >> 1)) * 1024 + (t & 1) * 32;
    const char* srcB = reinterpret_cast<const char*>(g_HsH)
                     + ((size_t)b * N_ + (t >> 4)) * 512 + (size_t)bn * 2 + (t & 15) * 16;
    const uint32_t soa = sb + AUX_SZ + OFF_A + (t >> 1) * A_ROW + (t & 1) * 32;
    const uint32_t sob = sb + AUX_SZ + OFF_B + (t >> 4) * B_ROW + (t & 15) * 16;

    auto issue = [&](int s, uint32_t buf) {
        uint32_t st = buf * STAGE;
        cpa16(soa + st,      srcA + s * 64);
        cpa16(soa + st + 16, srcA + s * 64 + 16);
        cpa16(sob + st,            srcB + (size_t)s * 16384);
        cpa16(sob + st + 16 * B_ROW, srcB + (size_t)s * 16384 + 16 * 512);
    };

    float acc[4][4][4];
#pragma unroll
    for (int i = 0; i < 4; i++)
#pragma unroll
        for (int j = 0; j < 4; j++)
#pragma unroll
            for (int e = 0; e < 4; e++) acc[i][j][e] = 0.f;

    const int S = N_ / KC;  // 16
#pragma unroll
    for (int p = 0; p < 3; p++) { issue(p, p); CP_COMMIT(); }

    for (int s = 0; s < S; s++) {
        CP_WAIT(2);
        __syncthreads();
        if (s + 3 < S) issue(s + 3, (uint32_t)((s + 3) & 3));
        CP_COMMIT();
        chunk_mma32(acc, sb + AUX_SZ + (uint32_t)(s & 3) * STAGE, wm, wn, lane);
    }

    // epilogue: + self-loop Hs[i,o] (fp16), * mask*dis_i, relu
    const int g = lane >> 2, i4 = lane & 3;
#pragma unroll
    for (int mi = 0; mi < 4; mi++) {
        int r0 = wm * 64 + mi * 16 + g;
        float md0 = mdis_s[r0], md1 = mdis_s[r0 + 8];
        size_t row0 = ((size_t)b * N_ + i0 + r0) * O_ + bn;
        size_t row1 = row0 + 8 * O_;
#pragma unroll
        for (int n = 0; n < 4; n++) {
            int o = wn * 32 + n * 8 + i4 * 2;
            float2 s0 = unpackh2(g_HsH[(row0 + o) >> 1]);
            float2 s1 = unpackh2(g_HsH[(row1 + o) >> 1]);
            out[row0 + o]     = fmaxf(0.f, md0 * (acc[mi][n][0] + s0.x));
            out[row0 + o + 1] = fmaxf(0.f, md0 * (acc[mi][n][1] + s0.y));
            out[row1 + o]     = fmaxf(0.f, md1 * (acc[mi][n][2] + s1.x));
            out[row1 + o + 1] = fmaxf(0.f, md1 * (acc[mi][n][3] + s1.y));
        }
    }
}

// ---------------------------------------------------------------------------
extern "C" void kernel_launch(void* const* d_in, const int* in_sizes, int n_in,
                              void* d_out, int out_size) {
    const float* H    = (const float*)d_in[0];
    const float* A    = (const float*)d_in[1];
    const float* mask = (const float*)d_in[2];
    const float* W    = (const float*)d_in[3];
    const float* bias = (const float*)d_in[4];
    float* out = (float*)d_out;

    cudaFuncSetAttribute(gemm1_mma, cudaFuncAttributeMaxDynamicSharedMemorySize, SMEM_TOTAL);
    cudaFuncSetAttribute(gemm2_mma, cudaFuncAttributeMaxDynamicSharedMemorySize, SMEM_TOTAL);

    prep_kernel<<<832, 256>>>(A, H, W);
    gemm1_mma<<<dim3(128, 2), 256, SMEM_TOTAL>>>(bias);
    gemm2_mma<<<dim3(4, 2, B_), 256, SMEM_TOTAL>>>(mask, out);
}